// round 1
// baseline (speedup 1.0000x reference)
#include <cuda_runtime.h>
#include <cuda_bf16.h>

// Problem constants
constexpr int B  = 8;
constexpr int C  = 256;
constexpr int H  = 64;
constexpr int W  = 64;
constexpr int HW = H * W;          // 4096
constexpr int K2 = 9;
constexpr int DG = 4;
constexpr int CG = C / DG;         // 64 channels per deform group
constexpr int CK = C * K2;         // 2304 GEMM K dimension
constexpr int GN = 32;             // groupnorm groups
constexpr int CPG = C / GN;        // 8 channels per gn group

// Scratch (static device arrays; no runtime allocation allowed)
__device__ float g_col[(size_t)B * CK * HW];   // 302 MB: col[b][ci*9+k][p]
__device__ float g_conv[(size_t)B * C * HW];   // 33.5 MB: conv output before GN

// ---------------------------------------------------------------------------
// Kernel 1: offset projection + deformable bilinear im2col
// grid: (16 p-tiles, 36 = g*9+k, 8 b), block: 256 threads (one per position)
// ---------------------------------------------------------------------------
__global__ void im2col_kernel(const float* __restrict__ x,
                              const float* __restrict__ shp,
                              const float* __restrict__ w_offset)
{
    const int p  = blockIdx.x * 256 + threadIdx.x;   // 0..4095
    const int gk = blockIdx.y;                       // 0..35
    const int b  = blockIdx.z;
    const int g  = gk / K2;
    const int k  = gk % K2;
    const int h  = p >> 6;
    const int w  = p & 63;

    // shape values for this pixel
    const float* sp = shp + (size_t)b * 4 * HW + p;
    const float s0 = sp[0], s1 = sp[HW], s2 = sp[2 * HW], s3 = sp[3 * HW];

    // offset = w_offset[(g*9+k)*2 + {0,1}] . shape
    const float* wo = w_offset + (size_t)gk * 2 * 4;
    const float dy = wo[0] * s0 + wo[1] * s1 + wo[2] * s2 + wo[3] * s3;
    const float dx = wo[4] * s0 + wo[5] * s1 + wo[6] * s2 + wo[7] * s3;

    const float py = dy + (float)(k / 3 - 1) + (float)h;
    const float px = dx + (float)(k % 3 - 1) + (float)w;

    const float y0f = floorf(py);
    const float x0f = floorf(px);
    const float ly = py - y0f;
    const float lx = px - x0f;
    const int iy0 = (int)y0f, ix0 = (int)x0f;
    const int iy1 = iy0 + 1,  ix1 = ix0 + 1;

    const bool vy0 = (iy0 >= 0) && (iy0 <= H - 1);
    const bool vy1 = (iy1 >= 0) && (iy1 <= H - 1);
    const bool vx0 = (ix0 >= 0) && (ix0 <= W - 1);
    const bool vx1 = (ix1 >= 0) && (ix1 <= W - 1);

    const int yc0 = min(max(iy0, 0), H - 1);
    const int yc1 = min(max(iy1, 0), H - 1);
    const int xc0 = min(max(ix0, 0), W - 1);
    const int xc1 = min(max(ix1, 0), W - 1);

    const float w00 = (1.f - ly) * (1.f - lx) * ((vy0 && vx0) ? 1.f : 0.f);
    const float w01 = (1.f - ly) * lx         * ((vy0 && vx1) ? 1.f : 0.f);
    const float w10 = ly * (1.f - lx)         * ((vy1 && vx0) ? 1.f : 0.f);
    const float w11 = ly * lx                 * ((vy1 && vx1) ? 1.f : 0.f);

    const int a00 = yc0 * W + xc0;
    const int a01 = yc0 * W + xc1;
    const int a10 = yc1 * W + xc0;
    const int a11 = yc1 * W + xc1;

    const float* xb = x + ((size_t)b * C + (size_t)g * CG) * HW;
    float* colp = g_col + (size_t)b * CK * HW + ((size_t)(g * CG) * K2 + k) * HW + p;

    #pragma unroll 4
    for (int ci = 0; ci < CG; ci++) {
        const float* img = xb + (size_t)ci * HW;
        float v = w00 * img[a00] + w01 * img[a01] + w10 * img[a10] + w11 * img[a11];
        colp[(size_t)ci * K2 * HW] = v;
    }
}

// ---------------------------------------------------------------------------
// Kernel 2: batched GEMM  conv[b][m][p] = sum_k A[m][k] * col[b][k][p]
// A = w_deform viewed as [256][2304] row-major (ck = ci*9 + k matches col)
// Tiles: BM=64, BN=64, BK=16; 256 threads; 4x4 register tile per thread.
// ---------------------------------------------------------------------------
constexpr int BM = 64, BN = 64, BK = 16;

__global__ void gemm_kernel(const float* __restrict__ A)
{
    __shared__ float As[BK][BM + 4];
    __shared__ float Bs[BK][BN];

    const int b  = blockIdx.z;
    const int m0 = blockIdx.x * BM;     // gridDim.x = 4
    const int n0 = blockIdx.y * BN;     // gridDim.y = 64
    const int tid = threadIdx.x;        // 256
    const int tx = tid & 15;
    const int ty = tid >> 4;

    const float* Bp = g_col + (size_t)b * CK * HW;

    // A load map: thread t -> A[m0 + t/4][kt + (t%4)*4 .. +3]
    const int am = tid >> 2;
    const int ak = (tid & 3) * 4;
    // B load map: thread t -> B[kt + t/16][n0 + (t%16)*4 .. +3]
    const int bk = tid >> 4;
    const int bn = (tid & 15) * 4;

    float acc[4][4] = {};

    for (int kt = 0; kt < CK; kt += BK) {
        float4 av = *(const float4*)(A + (size_t)(m0 + am) * CK + kt + ak);
        As[ak + 0][am] = av.x;
        As[ak + 1][am] = av.y;
        As[ak + 2][am] = av.z;
        As[ak + 3][am] = av.w;
        float4 bv = *(const float4*)(Bp + (size_t)(kt + bk) * HW + n0 + bn);
        *(float4*)&Bs[bk][bn] = bv;
        __syncthreads();

        #pragma unroll
        for (int kk = 0; kk < BK; kk++) {
            float4 ra = *(const float4*)&As[kk][ty * 4];
            float4 rb = *(const float4*)&Bs[kk][tx * 4];
            float fa[4] = {ra.x, ra.y, ra.z, ra.w};
            float fb[4] = {rb.x, rb.y, rb.z, rb.w};
            #pragma unroll
            for (int i = 0; i < 4; i++)
                #pragma unroll
                for (int j = 0; j < 4; j++)
                    acc[i][j] += fa[i] * fb[j];
        }
        __syncthreads();
    }

    float* Cp = g_conv + (size_t)b * C * HW;
    #pragma unroll
    for (int i = 0; i < 4; i++) {
        float4 v = make_float4(acc[i][0], acc[i][1], acc[i][2], acc[i][3]);
        *(float4*)&Cp[(size_t)(m0 + ty * 4 + i) * HW + n0 + tx * 4] = v;
    }
}

// ---------------------------------------------------------------------------
// Kernel 3: GroupNorm (32 groups of 8 channels over HxW) + affine + ReLU
// one block (256 threads) per (b, group): reduce 8*4096 values, normalize.
// ---------------------------------------------------------------------------
__global__ void gn_kernel(const float* __restrict__ gamma,
                          const float* __restrict__ beta,
                          float* __restrict__ out)
{
    const int bg = blockIdx.x;          // 0..255
    const int b  = bg / GN;
    const int gn = bg % GN;
    const int tid = threadIdx.x;        // 256
    const int NELEM = CPG * HW;         // 32768

    const float* src = g_conv + ((size_t)b * C + (size_t)gn * CPG) * HW;

    float s = 0.f, ss = 0.f;
    for (int i = tid; i < NELEM; i += 256) {
        float v = src[i];
        s += v;
        ss += v * v;
    }

    __shared__ float rs[256], rss[256];
    rs[tid] = s; rss[tid] = ss;
    __syncthreads();
    for (int st = 128; st > 0; st >>= 1) {
        if (tid < st) { rs[tid] += rs[tid + st]; rss[tid] += rss[tid + st]; }
        __syncthreads();
    }
    const float inv_n = 1.f / (float)NELEM;
    const float mu = rs[0] * inv_n;
    const float var = rss[0] * inv_n - mu * mu;
    const float rstd = rsqrtf(var + 1e-5f);

    float* dst = out + ((size_t)b * C + (size_t)gn * CPG) * HW;
    for (int i = tid; i < NELEM; i += 256) {
        const int c = gn * CPG + (i >> 12);   // i / HW
        float v = (src[i] - mu) * rstd * gamma[c] + beta[c];
        dst[i] = fmaxf(v, 0.f);
    }
}

// ---------------------------------------------------------------------------
extern "C" void kernel_launch(void* const* d_in, const int* in_sizes, int n_in,
                              void* d_out, int out_size)
{
    const float* x        = (const float*)d_in[0];
    const float* shp      = (const float*)d_in[1];
    const float* w_offset = (const float*)d_in[2];
    const float* w_deform = (const float*)d_in[3];
    const float* gamma    = (const float*)d_in[4];
    const float* beta     = (const float*)d_in[5];
    float* out = (float*)d_out;

    dim3 g1(HW / 256, DG * K2, B);          // (16, 36, 8)
    im2col_kernel<<<g1, 256>>>(x, shp, w_offset);

    dim3 g2(C / BM, HW / BN, B);            // (4, 64, 8)
    gemm_kernel<<<g2, 256>>>(w_deform);

    gn_kernel<<<B * GN, 256>>>(gamma, beta, out);
}

// round 3
// speedup vs baseline: 3.9335x; 3.9335x over previous
#include <cuda_runtime.h>
#include <cuda_fp16.h>
#include <cstdint>

// Problem constants
constexpr int B  = 8;
constexpr int C  = 256;
constexpr int H  = 64;
constexpr int W  = 64;
constexpr int HW = H * W;          // 4096
constexpr int K2 = 9;
constexpr int DG = 4;
constexpr int CG = C / DG;         // 64
constexpr int CK = C * K2;         // 2304
constexpr int GN = 32;
constexpr int CPG = C / GN;        // 8

// Scratch (static device arrays)
__device__ __align__(16) __half g_col[(size_t)B * CK * HW];   // 151 MB col[b][ck][p] fp16
__device__ __align__(16) __half g_A[(size_t)C * CK];          // 1.18 MB weights fp16
__device__ float g_conv[(size_t)B * C * HW];                  // 33.5 MB conv output

// ---------------------------------------------------------------------------
// PTX helpers (baseline PTX only — no tcgen05; toolchain targets compute_103)
// ---------------------------------------------------------------------------
__device__ __forceinline__ uint32_t smem_u32(const void* p) {
    uint32_t a;
    asm("{ .reg .u64 t; cvta.to.shared.u64 t, %1; cvt.u32.u64 %0, t; }" : "=r"(a) : "l"(p));
    return a;
}
__device__ __forceinline__ void cpa16(uint32_t s, const void* g) {
    asm volatile("cp.async.cg.shared.global [%0], [%1], 16;" :: "r"(s), "l"(g));
}
#define CPA_COMMIT() asm volatile("cp.async.commit_group;" ::: "memory")

__device__ __forceinline__ void ldsm_x4(uint32_t& r0, uint32_t& r1, uint32_t& r2,
                                        uint32_t& r3, uint32_t addr) {
    asm volatile("ldmatrix.sync.aligned.m8n8.x4.shared.b16 {%0,%1,%2,%3}, [%4];"
                 : "=r"(r0), "=r"(r1), "=r"(r2), "=r"(r3) : "r"(addr));
}
__device__ __forceinline__ void ldsm_x4_t(uint32_t& r0, uint32_t& r1, uint32_t& r2,
                                          uint32_t& r3, uint32_t addr) {
    asm volatile("ldmatrix.sync.aligned.m8n8.x4.trans.shared.b16 {%0,%1,%2,%3}, [%4];"
                 : "=r"(r0), "=r"(r1), "=r"(r2), "=r"(r3) : "r"(addr));
}
__device__ __forceinline__ void mma16816(float* c, const uint32_t* a, const uint32_t* b) {
    asm volatile(
        "mma.sync.aligned.m16n8k16.row.col.f32.f16.f16.f32 "
        "{%0,%1,%2,%3}, {%4,%5,%6,%7}, {%8,%9}, {%0,%1,%2,%3};"
        : "+f"(c[0]), "+f"(c[1]), "+f"(c[2]), "+f"(c[3])
        : "r"(a[0]), "r"(a[1]), "r"(a[2]), "r"(a[3]), "r"(b[0]), "r"(b[1]));
}

// ---------------------------------------------------------------------------
// Kernel 0: fp32 -> fp16 weight convert
// ---------------------------------------------------------------------------
__global__ void wconv_kernel(const float* __restrict__ w) {
    int i = blockIdx.x * 1024 + threadIdx.x;
    if (i < C * CK) g_A[i] = __float2half(w[i]);
}

// ---------------------------------------------------------------------------
// Kernel 1: offset projection + deformable bilinear im2col (fp16 output)
// ---------------------------------------------------------------------------
__global__ void im2col_kernel(const float* __restrict__ x,
                              const float* __restrict__ shp,
                              const float* __restrict__ w_offset)
{
    const int p  = blockIdx.x * 256 + threadIdx.x;
    const int gk = blockIdx.y;                       // 0..35
    const int b  = blockIdx.z;
    const int g  = gk / K2;
    const int k  = gk % K2;
    const int h  = p >> 6;
    const int w  = p & 63;

    const float* sp = shp + (size_t)b * 4 * HW + p;
    const float s0 = sp[0], s1 = sp[HW], s2 = sp[2 * HW], s3 = sp[3 * HW];

    const float* wo = w_offset + (size_t)gk * 2 * 4;
    const float dy = wo[0] * s0 + wo[1] * s1 + wo[2] * s2 + wo[3] * s3;
    const float dx = wo[4] * s0 + wo[5] * s1 + wo[6] * s2 + wo[7] * s3;

    const float py = dy + (float)(k / 3 - 1) + (float)h;
    const float px = dx + (float)(k % 3 - 1) + (float)w;

    const float y0f = floorf(py);
    const float x0f = floorf(px);
    const float ly = py - y0f;
    const float lx = px - x0f;
    const int iy0 = (int)y0f, ix0 = (int)x0f;
    const int iy1 = iy0 + 1,  ix1 = ix0 + 1;

    const bool vy0 = (iy0 >= 0) && (iy0 <= H - 1);
    const bool vy1 = (iy1 >= 0) && (iy1 <= H - 1);
    const bool vx0 = (ix0 >= 0) && (ix0 <= W - 1);
    const bool vx1 = (ix1 >= 0) && (ix1 <= W - 1);

    const int yc0 = min(max(iy0, 0), H - 1);
    const int yc1 = min(max(iy1, 0), H - 1);
    const int xc0 = min(max(ix0, 0), W - 1);
    const int xc1 = min(max(ix1, 0), W - 1);

    const float w00 = (1.f - ly) * (1.f - lx) * ((vy0 && vx0) ? 1.f : 0.f);
    const float w01 = (1.f - ly) * lx         * ((vy0 && vx1) ? 1.f : 0.f);
    const float w10 = ly * (1.f - lx)         * ((vy1 && vx0) ? 1.f : 0.f);
    const float w11 = ly * lx                 * ((vy1 && vx1) ? 1.f : 0.f);

    const int a00 = yc0 * W + xc0;
    const int a01 = yc0 * W + xc1;
    const int a10 = yc1 * W + xc0;
    const int a11 = yc1 * W + xc1;

    const float* xb = x + ((size_t)b * C + (size_t)g * CG) * HW;
    __half* colp = g_col + (size_t)b * CK * HW + ((size_t)(g * CG) * K2 + k) * HW + p;

    #pragma unroll 4
    for (int ci = 0; ci < CG; ci++) {
        const float* img = xb + (size_t)ci * HW;
        float v = w00 * img[a00] + w01 * img[a01] + w10 * img[a10] + w11 * img[a11];
        colp[(size_t)ci * K2 * HW] = __float2half(v);
    }
}

// ---------------------------------------------------------------------------
// Kernel 2: HMMA (mma.sync m16n8k16) GEMM
//   conv[b][m][p] = sum_ck A[m][ck] * col[b][ck][p]
// CTA tile: BM=256 (all M), BN=64, BK=32. 8 warps (4 m x 2 n), 64x32 per warp.
// col is read exactly once from HBM; A stays resident in L2.
// ---------------------------------------------------------------------------
constexpr int BM = 256, BN = 64, BK = 32;
constexpr int NT = CK / BK;               // 72
constexpr int A_STRIDE = BK + 8;          // 40 halfs (80B rows, 16B aligned)
constexpr int B_STRIDE = BN + 8;          // 72 halfs (144B rows, 16B aligned)
constexpr int A_BUF = BM * A_STRIDE;      // 10240 halfs
constexpr int B_BUF = BK * B_STRIDE;      // 2304 halfs
constexpr uint32_t GEMM_SMEM = 2 * (A_BUF + B_BUF) * 2;  // 50176 B

__global__ __launch_bounds__(256) void gemm_kernel()
{
    extern __shared__ __half sm[];
    __half* Asm = sm;                     // [2][BM][A_STRIDE]
    __half* Bsm = sm + 2 * A_BUF;         // [2][BK][B_STRIDE]

    const int tid  = threadIdx.x;
    const int lane = tid & 31;
    const int warp = tid >> 5;
    const int n0   = blockIdx.x * BN;
    const int b    = blockIdx.y;
    const int wm   = (warp >> 1) * 64;    // warp m-base (0,64,128,192)
    const int wn   = (warp & 1) * 32;     // warp n-base (0,32)

    const uint32_t sA = smem_u32(Asm);
    const uint32_t sB = smem_u32(Bsm);

    // per-thread load maps
    const int ar = tid >> 2 << 2;          // not used; keep simple below

    auto load_tile = [&](int kt, int j) {
        const __half* ga = g_A + kt * BK;
        const uint32_t dA = sA + j * A_BUF * 2;
        #pragma unroll
        for (int it = 0; it < 4; it++) {
            int c = it * 256 + tid;        // 0..1023
            int r = c >> 2, s = c & 3;
            cpa16(dA + (uint32_t)(r * A_STRIDE + s * 8) * 2,
                  ga + (size_t)r * CK + s * 8);
        }
        const __half* gb = g_col + ((size_t)b * CK + (size_t)kt * BK) * HW + n0;
        const uint32_t dB = sB + j * B_BUF * 2;
        {
            int r = tid >> 3, s = tid & 7;  // 32 rows x 8 chunks
            cpa16(dB + (uint32_t)(r * B_STRIDE + s * 8) * 2,
                  gb + (size_t)r * HW + s * 8);
        }
        CPA_COMMIT();
    };

    float acc[4][4][4];
    #pragma unroll
    for (int i = 0; i < 4; i++)
        #pragma unroll
        for (int n = 0; n < 4; n++)
            #pragma unroll
            for (int q = 0; q < 4; q++) acc[i][n][q] = 0.f;

    load_tile(0, 0);

    for (int kt = 0; kt < NT; kt++) {
        const int j = kt & 1;
        if (kt + 1 < NT) {
            load_tile(kt + 1, j ^ 1);
            asm volatile("cp.async.wait_group 1;" ::: "memory");
        } else {
            asm volatile("cp.async.wait_group 0;" ::: "memory");
        }
        __syncthreads();

        const uint32_t aBase = sA + j * A_BUF * 2;
        const uint32_t bBase = sB + j * B_BUF * 2;

        #pragma unroll
        for (int kk = 0; kk < 2; kk++) {
            uint32_t a[4][4];
            #pragma unroll
            for (int i = 0; i < 4; i++) {
                uint32_t addr = aBase +
                    (uint32_t)((wm + i * 16 + (lane & 15)) * A_STRIDE +
                               kk * 16 + (lane >> 4) * 8) * 2;
                ldsm_x4(a[i][0], a[i][1], a[i][2], a[i][3], addr);
            }
            uint32_t bb[4][2];
            #pragma unroll
            for (int p = 0; p < 2; p++) {
                uint32_t addr = bBase +
                    (uint32_t)((kk * 16 + (lane & 15)) * B_STRIDE +
                               wn + p * 16 + (lane >> 4) * 8) * 2;
                uint32_t r0, r1, r2, r3;
                ldsm_x4_t(r0, r1, r2, r3, addr);
                bb[2 * p][0] = r0; bb[2 * p][1] = r1;
                bb[2 * p + 1][0] = r2; bb[2 * p + 1][1] = r3;
            }
            #pragma unroll
            for (int i = 0; i < 4; i++)
                #pragma unroll
                for (int n = 0; n < 4; n++)
                    mma16816(acc[i][n], a[i], bb[n]);
        }
        __syncthreads();
    }

    // Epilogue: fp32 stores to g_conv
    #pragma unroll
    for (int i = 0; i < 4; i++) {
        const int m = wm + i * 16 + (lane >> 2);
        float* row0 = g_conv + ((size_t)b * C + m) * HW + n0 + wn;
        float* row1 = row0 + (size_t)8 * HW;
        #pragma unroll
        for (int n = 0; n < 4; n++) {
            const int col = n * 8 + (lane & 3) * 2;
            *(float2*)(row0 + col) = make_float2(acc[i][n][0], acc[i][n][1]);
            *(float2*)(row1 + col) = make_float2(acc[i][n][2], acc[i][n][3]);
        }
    }
    (void)ar;
}

// ---------------------------------------------------------------------------
// Kernel 3: GroupNorm + affine + ReLU
// ---------------------------------------------------------------------------
__global__ void gn_kernel(const float* __restrict__ gamma,
                          const float* __restrict__ beta,
                          float* __restrict__ out)
{
    const int bg = blockIdx.x;
    const int b  = bg / GN;
    const int gn = bg % GN;
    const int tid = threadIdx.x;
    const int NELEM = CPG * HW;            // 32768

    const float* src = g_conv + ((size_t)b * C + (size_t)gn * CPG) * HW;

    float s = 0.f, ss = 0.f;
    for (int i = tid; i < NELEM; i += 256) {
        float v = src[i];
        s += v; ss += v * v;
    }
    __shared__ float rs[256], rss[256];
    rs[tid] = s; rss[tid] = ss;
    __syncthreads();
    for (int st = 128; st > 0; st >>= 1) {
        if (tid < st) { rs[tid] += rs[tid + st]; rss[tid] += rss[tid + st]; }
        __syncthreads();
    }
    const float inv_n = 1.f / (float)NELEM;
    const float mu = rs[0] * inv_n;
    const float var = rss[0] * inv_n - mu * mu;
    const float rstd = rsqrtf(var + 1e-5f);

    float* dst = out + ((size_t)b * C + (size_t)gn * CPG) * HW;
    for (int i = tid; i < NELEM; i += 256) {
        const int c = gn * CPG + (i >> 12);
        float v = (src[i] - mu) * rstd * gamma[c] + beta[c];
        dst[i] = fmaxf(v, 0.f);
    }
}

// ---------------------------------------------------------------------------
extern "C" void kernel_launch(void* const* d_in, const int* in_sizes, int n_in,
                              void* d_out, int out_size)
{
    const float* x        = (const float*)d_in[0];
    const float* shp      = (const float*)d_in[1];
    const float* w_offset = (const float*)d_in[2];
    const float* w_deform = (const float*)d_in[3];
    const float* gamma    = (const float*)d_in[4];
    const float* beta     = (const float*)d_in[5];
    float* out = (float*)d_out;

    static bool attr_set = false;
    if (!attr_set) {
        cudaFuncSetAttribute(gemm_kernel, cudaFuncAttributeMaxDynamicSharedMemorySize,
                             GEMM_SMEM);
        attr_set = true;
    }

    wconv_kernel<<<(C * CK + 1023) / 1024, 1024>>>(w_deform);

    dim3 g1(HW / 256, DG * K2, B);
    im2col_kernel<<<g1, 256>>>(x, shp, w_offset);

    dim3 g2(HW / BN, B);                   // (64, 8)
    gemm_kernel<<<g2, 256, GEMM_SMEM>>>();

    gn_kernel<<<B * GN, 256>>>(gamma, beta, out);
}

// round 4
// speedup vs baseline: 4.4780x; 1.1384x over previous
#include <cuda_runtime.h>
#include <cuda_fp16.h>
#include <cstdint>

// Problem constants
constexpr int B  = 8;
constexpr int C  = 256;
constexpr int H  = 64;
constexpr int W  = 64;
constexpr int HW = H * W;          // 4096
constexpr int K2 = 9;
constexpr int DG = 4;
constexpr int CG = C / DG;         // 64
constexpr int CK = C * K2;         // 2304
constexpr int GN = 32;
constexpr int CPG = C / GN;        // 8

// Scratch (static device arrays)
__device__ __align__(16) __half g_col[(size_t)B * CK * HW];   // 151 MB col[b][ck][p] fp16
__device__ __align__(16) __half g_A[(size_t)C * CK];          // 1.18 MB weights fp16
__device__ float g_conv[(size_t)B * C * HW];                  // 33.5 MB conv output
__device__ float g_gsum[B * GN];                              // group partial sums
__device__ float g_gss[B * GN];                               // group partial sum-squares
__device__ float g_mu[B * GN];                                // finalized mean
__device__ float g_rstd[B * GN];                              // finalized rstd

// ---------------------------------------------------------------------------
// PTX helpers (baseline PTX only — toolchain targets compute_103, no tcgen05)
// ---------------------------------------------------------------------------
__device__ __forceinline__ uint32_t smem_u32(const void* p) {
    uint32_t a;
    asm("{ .reg .u64 t; cvta.to.shared.u64 t, %1; cvt.u32.u64 %0, t; }" : "=r"(a) : "l"(p));
    return a;
}
__device__ __forceinline__ void cpa16(uint32_t s, const void* g) {
    asm volatile("cp.async.cg.shared.global [%0], [%1], 16;" :: "r"(s), "l"(g));
}
#define CPA_COMMIT() asm volatile("cp.async.commit_group;" ::: "memory")

__device__ __forceinline__ void ldsm_x4(uint32_t& r0, uint32_t& r1, uint32_t& r2,
                                        uint32_t& r3, uint32_t addr) {
    asm volatile("ldmatrix.sync.aligned.m8n8.x4.shared.b16 {%0,%1,%2,%3}, [%4];"
                 : "=r"(r0), "=r"(r1), "=r"(r2), "=r"(r3) : "r"(addr));
}
__device__ __forceinline__ void ldsm_x4_t(uint32_t& r0, uint32_t& r1, uint32_t& r2,
                                          uint32_t& r3, uint32_t addr) {
    asm volatile("ldmatrix.sync.aligned.m8n8.x4.trans.shared.b16 {%0,%1,%2,%3}, [%4];"
                 : "=r"(r0), "=r"(r1), "=r"(r2), "=r"(r3) : "r"(addr));
}
__device__ __forceinline__ void mma16816(float* c, const uint32_t* a, const uint32_t* b) {
    asm volatile(
        "mma.sync.aligned.m16n8k16.row.col.f32.f16.f16.f32 "
        "{%0,%1,%2,%3}, {%4,%5,%6,%7}, {%8,%9}, {%0,%1,%2,%3};"
        : "+f"(c[0]), "+f"(c[1]), "+f"(c[2]), "+f"(c[3])
        : "r"(a[0]), "r"(a[1]), "r"(a[2]), "r"(a[3]), "r"(b[0]), "r"(b[1]));
}

// ---------------------------------------------------------------------------
// Kernel 0: fp32 -> fp16 weight convert + zero GN accumulators
// ---------------------------------------------------------------------------
__global__ void wconv_kernel(const float* __restrict__ w) {
    int i = blockIdx.x * 1024 + threadIdx.x;
    if (i < C * CK) g_A[i] = __float2half(w[i]);
    if (blockIdx.x == 0 && threadIdx.x < B * GN) {
        g_gsum[threadIdx.x] = 0.f;
        g_gss[threadIdx.x]  = 0.f;
    }
}

// ---------------------------------------------------------------------------
// Kernel 1: offset projection + deformable bilinear im2col (fp16 output)
// ---------------------------------------------------------------------------
__global__ void im2col_kernel(const float* __restrict__ x,
                              const float* __restrict__ shp,
                              const float* __restrict__ w_offset)
{
    const int p  = blockIdx.x * 256 + threadIdx.x;
    const int gk = blockIdx.y;                       // 0..35
    const int b  = blockIdx.z;
    const int g  = gk / K2;
    const int k  = gk % K2;
    const int h  = p >> 6;
    const int w  = p & 63;

    const float* sp = shp + (size_t)b * 4 * HW + p;
    const float s0 = sp[0], s1 = sp[HW], s2 = sp[2 * HW], s3 = sp[3 * HW];

    const float* wo = w_offset + (size_t)gk * 2 * 4;
    const float dy = wo[0] * s0 + wo[1] * s1 + wo[2] * s2 + wo[3] * s3;
    const float dx = wo[4] * s0 + wo[5] * s1 + wo[6] * s2 + wo[7] * s3;

    const float py = dy + (float)(k / 3 - 1) + (float)h;
    const float px = dx + (float)(k % 3 - 1) + (float)w;

    const float y0f = floorf(py);
    const float x0f = floorf(px);
    const float ly = py - y0f;
    const float lx = px - x0f;
    const int iy0 = (int)y0f, ix0 = (int)x0f;
    const int iy1 = iy0 + 1,  ix1 = ix0 + 1;

    const bool vy0 = (iy0 >= 0) && (iy0 <= H - 1);
    const bool vy1 = (iy1 >= 0) && (iy1 <= H - 1);
    const bool vx0 = (ix0 >= 0) && (ix0 <= W - 1);
    const bool vx1 = (ix1 >= 0) && (ix1 <= W - 1);

    const int yc0 = min(max(iy0, 0), H - 1);
    const int yc1 = min(max(iy1, 0), H - 1);
    const int xc0 = min(max(ix0, 0), W - 1);
    const int xc1 = min(max(ix1, 0), W - 1);

    const float w00 = (1.f - ly) * (1.f - lx) * ((vy0 && vx0) ? 1.f : 0.f);
    const float w01 = (1.f - ly) * lx         * ((vy0 && vx1) ? 1.f : 0.f);
    const float w10 = ly * (1.f - lx)         * ((vy1 && vx0) ? 1.f : 0.f);
    const float w11 = ly * lx                 * ((vy1 && vx1) ? 1.f : 0.f);

    const int a00 = yc0 * W + xc0;
    const int a01 = yc0 * W + xc1;
    const int a10 = yc1 * W + xc0;
    const int a11 = yc1 * W + xc1;

    const float* xb = x + ((size_t)b * C + (size_t)g * CG) * HW;
    __half* colp = g_col + (size_t)b * CK * HW + ((size_t)(g * CG) * K2 + k) * HW + p;

    #pragma unroll 4
    for (int ci = 0; ci < CG; ci++) {
        const float* img = xb + (size_t)ci * HW;
        float v = w00 * img[a00] + w01 * img[a01] + w10 * img[a10] + w11 * img[a11];
        colp[(size_t)ci * K2 * HW] = __float2half(v);
    }
}

// ---------------------------------------------------------------------------
// Kernel 2: HMMA GEMM + fused GN partial statistics
//   conv[b][m][p] = sum_ck A[m][ck] * col[b][ck][p]
// CTA tile: BM=256 (all M), BN=64, BK=64; 8 warps (4m x 2n), 64x32 per warp.
// ---------------------------------------------------------------------------
constexpr int BM = 256, BN = 64, BK = 64;
constexpr int NT = CK / BK;               // 36
constexpr int A_STRIDE = BK + 8;          // 72 halfs (144 B rows)
constexpr int B_STRIDE = BN + 8;          // 72 halfs
constexpr int A_BUF = BM * A_STRIDE;      // 18432 halfs
constexpr int B_BUF = BK * B_STRIDE;      // 4608 halfs
constexpr uint32_t GEMM_SMEM = 2 * (A_BUF + B_BUF) * 2;  // 92160 B

__global__ void __launch_bounds__(256, 2) gemm_kernel()
{
    extern __shared__ __half sm[];
    __half* Asm = sm;                     // [2][BM][A_STRIDE]
    __half* Bsm = sm + 2 * A_BUF;         // [2][BK][B_STRIDE]

    const int tid  = threadIdx.x;
    const int lane = tid & 31;
    const int warp = tid >> 5;
    const int n0   = blockIdx.x * BN;
    const int b    = blockIdx.y;
    const int wm   = (warp >> 1) * 64;    // 0,64,128,192
    const int wn   = (warp & 1) * 32;     // 0,32

    const uint32_t sA = smem_u32(Asm);
    const uint32_t sB = smem_u32(Bsm);

    auto load_tile = [&](int kt, int j) {
        const __half* ga = g_A + (size_t)kt * BK;
        const uint32_t dA = sA + j * A_BUF * 2;
        #pragma unroll
        for (int it = 0; it < 8; it++) {
            int c = it * 256 + tid;        // 0..2047
            int r = c >> 3, s = c & 7;
            cpa16(dA + (uint32_t)(r * A_STRIDE + s * 8) * 2,
                  ga + (size_t)r * CK + s * 8);
        }
        const __half* gb = g_col + ((size_t)b * CK + (size_t)kt * BK) * HW + n0;
        const uint32_t dB = sB + j * B_BUF * 2;
        #pragma unroll
        for (int it = 0; it < 2; it++) {
            int c = it * 256 + tid;        // 0..511
            int r = c >> 3, s = c & 7;
            cpa16(dB + (uint32_t)(r * B_STRIDE + s * 8) * 2,
                  gb + (size_t)r * HW + s * 8);
        }
        CPA_COMMIT();
    };

    float acc[4][4][4];
    #pragma unroll
    for (int i = 0; i < 4; i++)
        #pragma unroll
        for (int n = 0; n < 4; n++)
            #pragma unroll
            for (int q = 0; q < 4; q++) acc[i][n][q] = 0.f;

    load_tile(0, 0);

    for (int kt = 0; kt < NT; kt++) {
        const int j = kt & 1;
        if (kt + 1 < NT) {
            load_tile(kt + 1, j ^ 1);
            asm volatile("cp.async.wait_group 1;" ::: "memory");
        } else {
            asm volatile("cp.async.wait_group 0;" ::: "memory");
        }
        __syncthreads();

        const uint32_t aBase = sA + j * A_BUF * 2;
        const uint32_t bBase = sB + j * B_BUF * 2;

        #pragma unroll
        for (int kk = 0; kk < 4; kk++) {
            uint32_t a[4][4];
            #pragma unroll
            for (int i = 0; i < 4; i++) {
                uint32_t addr = aBase +
                    (uint32_t)((wm + i * 16 + (lane & 15)) * A_STRIDE +
                               kk * 16 + (lane >> 4) * 8) * 2;
                ldsm_x4(a[i][0], a[i][1], a[i][2], a[i][3], addr);
            }
            uint32_t bb[4][2];
            #pragma unroll
            for (int p = 0; p < 2; p++) {
                uint32_t addr = bBase +
                    (uint32_t)((kk * 16 + (lane & 15)) * B_STRIDE +
                               wn + p * 16 + (lane >> 4) * 8) * 2;
                uint32_t r0, r1, r2, r3;
                ldsm_x4_t(r0, r1, r2, r3, addr);
                bb[2 * p][0] = r0;     bb[2 * p][1] = r1;
                bb[2 * p + 1][0] = r2; bb[2 * p + 1][1] = r3;
            }
            #pragma unroll
            for (int i = 0; i < 4; i++)
                #pragma unroll
                for (int n = 0; n < 4; n++)
                    mma16816(acc[i][n], a[i], bb[n]);
        }
        __syncthreads();
    }

    // ---- Epilogue: write conv + fused GN partial stats --------------------
    #pragma unroll
    for (int i = 0; i < 4; i++) {
        const int m = wm + i * 16 + (lane >> 2);
        float* row0 = g_conv + ((size_t)b * C + m) * HW + n0 + wn;
        float* row1 = row0 + (size_t)8 * HW;
        #pragma unroll
        for (int n = 0; n < 4; n++) {
            const int col = n * 8 + (lane & 3) * 2;
            *(float2*)(row0 + col) = make_float2(acc[i][n][0], acc[i][n][1]);
            *(float2*)(row1 + col) = make_float2(acc[i][n][2], acc[i][n][3]);
        }
    }

    // per-thread partial sums per (i, row0/row1)
    float* part = (float*)sm;              // reuse smem: [32][2] per group
    if (tid < 64) { part[tid] = 0.f; }
    __syncthreads();

    #pragma unroll
    for (int i = 0; i < 4; i++) {
        float s0 = 0.f, q0 = 0.f, s1 = 0.f, q1 = 0.f;
        #pragma unroll
        for (int n = 0; n < 4; n++) {
            s0 += acc[i][n][0] + acc[i][n][1];
            q0 += acc[i][n][0] * acc[i][n][0] + acc[i][n][1] * acc[i][n][1];
            s1 += acc[i][n][2] + acc[i][n][3];
            q1 += acc[i][n][2] * acc[i][n][2] + acc[i][n][3] * acc[i][n][3];
        }
        // reduce across lane&3 (same m-row)
        #pragma unroll
        for (int o = 1; o < 4; o <<= 1) {
            s0 += __shfl_xor_sync(0xffffffff, s0, o);
            q0 += __shfl_xor_sync(0xffffffff, q0, o);
            s1 += __shfl_xor_sync(0xffffffff, s1, o);
            q1 += __shfl_xor_sync(0xffffffff, q1, o);
        }
        if ((lane & 3) == 0) {
            const int m0 = wm + i * 16 + (lane >> 2);
            const int gi0 = m0 >> 3;           // group of row0
            const int gi1 = (m0 + 8) >> 3;     // group of row1
            atomicAdd(&part[gi0 * 2],     s0);
            atomicAdd(&part[gi0 * 2 + 1], q0);
            atomicAdd(&part[gi1 * 2],     s1);
            atomicAdd(&part[gi1 * 2 + 1], q1);
        }
    }
    __syncthreads();
    if (tid < 32) {
        atomicAdd(&g_gsum[b * GN + tid], part[tid * 2]);
        atomicAdd(&g_gss[b * GN + tid],  part[tid * 2 + 1]);
    }
}

// ---------------------------------------------------------------------------
// Kernel 3a: finalize GN stats
// ---------------------------------------------------------------------------
__global__ void gn_finalize_kernel()
{
    const int i = threadIdx.x;             // 0..255 = b*GN+g
    const float inv_n = 1.f / (float)(CPG * HW);
    const float mu  = g_gsum[i] * inv_n;
    const float var = g_gss[i] * inv_n - mu * mu;
    g_mu[i]   = mu;
    g_rstd[i] = rsqrtf(var + 1e-5f);
}

// ---------------------------------------------------------------------------
// Kernel 3b: normalize + affine + ReLU (fully parallel, float4)
// ---------------------------------------------------------------------------
__global__ void gn_norm_kernel(const float* __restrict__ gamma,
                               const float* __restrict__ beta,
                               float* __restrict__ out)
{
    const size_t i4 = ((size_t)blockIdx.x * 256 + threadIdx.x);   // float4 index
    const size_t i  = i4 * 4;
    const int c  = (int)((i >> 12) & 255);     // (i / HW) % C
    const int b  = (int)(i >> 20);             // i / (C*HW)
    const int gi = b * GN + (c >> 3);

    const float mu = g_mu[gi];
    const float rs = g_rstd[gi];
    const float ga = gamma[c] * rs;
    const float be = beta[c] - mu * ga;

    float4 v = *(const float4*)(g_conv + i);
    v.x = fmaxf(v.x * ga + be, 0.f);
    v.y = fmaxf(v.y * ga + be, 0.f);
    v.z = fmaxf(v.z * ga + be, 0.f);
    v.w = fmaxf(v.w * ga + be, 0.f);
    *(float4*)(out + i) = v;
}

// ---------------------------------------------------------------------------
extern "C" void kernel_launch(void* const* d_in, const int* in_sizes, int n_in,
                              void* d_out, int out_size)
{
    const float* x        = (const float*)d_in[0];
    const float* shp      = (const float*)d_in[1];
    const float* w_offset = (const float*)d_in[2];
    const float* w_deform = (const float*)d_in[3];
    const float* gamma    = (const float*)d_in[4];
    const float* beta     = (const float*)d_in[5];
    float* out = (float*)d_out;

    static bool attr_set = false;
    if (!attr_set) {
        cudaFuncSetAttribute(gemm_kernel, cudaFuncAttributeMaxDynamicSharedMemorySize,
                             GEMM_SMEM);
        attr_set = true;
    }

    wconv_kernel<<<(C * CK + 1023) / 1024, 1024>>>(w_deform);

    dim3 g1(HW / 256, DG * K2, B);
    im2col_kernel<<<g1, 256>>>(x, shp, w_offset);

    dim3 g2(HW / BN, B);                   // (64, 8)
    gemm_kernel<<<g2, 256, GEMM_SMEM>>>();

    gn_finalize_kernel<<<1, B * GN>>>();

    const size_t total4 = (size_t)B * C * HW / 4;   // 2,097,152
    gn_norm_kernel<<<(unsigned)(total4 / 256), 256>>>(gamma, beta, out);
}